// round 16
// baseline (speedup 1.0000x reference)
#include <cuda_runtime.h>
#include <math_constants.h>
#include <stdint.h>

#define BATCH   2
#define CNUM    81
#define NCLS    (CNUM - 1)
#define NP      CNUM
#define VCAP    512          // storage cap per chain (V never near this)
#define VMAX    128          // fast-path cap for matrix NMS
#define NMS_THR 0.3f
#define NT      512          // threads per CTA (2 chains x 256)
#define HT      256          // threads per chain
#define RPT     4            // hoisted scores per thread (HT*4 = 1024 >= R)
#define NBLK    (NCLS / 2 * BATCH)   // 80 CTAs

// det rows padded to 8 floats for vectorized access
__device__ __align__(16) float g_dets[BATCH][NCLS][NP][8];
__device__ int   g_cnt[BATCH][NCLS];
__device__ unsigned int g_done = 0;

// named barrier for one 256-thread chain (id 1 or 2)
#define CHAIN_SYNC(h) asm volatile("bar.sync %0, %1;" :: "r"((h) + 1), "r"(HT) : "memory")

__global__ void __launch_bounds__(NT)
fused_kernel(const float* __restrict__ cls_prob,   // (B,R,C)
             const float* __restrict__ rois,       // (B,R,5)
             const float* __restrict__ bbox_pred,  // (B,R,4C)
             const float* __restrict__ im_info,    // (B,3)
             const float* __restrict__ thr,        // (C,)
             float* __restrict__ out, int out_size,
             int R)
{
    const int tid  = threadIdx.x;
    const int h    = tid >> 8;          // chain (0/1)
    const int lt   = tid & (HT - 1);    // lane within chain
    const int lane = tid & 31;
    const int b    = blockIdx.y;
    const int cls  = blockIdx.x * 2 + h;   // 0..79
    const int c    = cls + 1;              // class id 1..80

    __shared__ unsigned long long ukey[2][VCAP];
    __shared__ float sx1[2][VCAP], sy1[2][VCAP], sx2[2][VCAP], sy2[2][VCAP], sar[2][VCAP];
    __shared__ unsigned long long sup[2][VMAX][2];
    __shared__ unsigned long long keptw[2][2];
    __shared__ unsigned char keep[2][VCAP];       // fallback only
    __shared__ int svcnt[2];
    __shared__ unsigned int is_last;
    __shared__ int cnts[BATCH][NCLS];
    __shared__ int incl[BATCH][NCLS];

    if (lt == 0) svcnt[h] = 0;
    CHAIN_SYNC(h);

    const float h_im = im_info[b * 3 + 0];
    const float w_im = im_info[b * 3 + 1];
    const float th   = thr[c];

    // ---- pass 1: hoisted score loads + warp-aggregated compaction ----
    float sc[RPT];
    #pragma unroll
    for (int it = 0; it < RPT; ++it) {
        const int rr = lt + it * HT;
        sc[it] = (rr < R) ? cls_prob[(size_t)(b * R + rr) * CNUM + c] : -1.0f;
    }
    #pragma unroll
    for (int it = 0; it < RPT; ++it) {
        const int rr = lt + it * HT;
        const bool valid = sc[it] > th;
        const unsigned mask = __ballot_sync(0xffffffffu, valid);
        if (mask) {
            const int leader = __ffs(mask) - 1;
            int base = 0;
            if (lane == leader) base = atomicAdd(&svcnt[h], __popc(mask));
            base = __shfl_sync(0xffffffffu, base, leader);
            if (valid) {
                const int pos = base + __popc(mask & ((1u << lane) - 1u));
                if (pos < VCAP) {
                    const uint32_t ub = __float_as_uint(sc[it]) ^ 0x80000000u;
                    ukey[h][pos] = ((unsigned long long)(~ub) << 32) | (uint32_t)rr;
                }
            }
        }
    }
    CHAIN_SYNC(h);

    const int V = min(svcnt[h], VCAP);

    // ---- fused decode + rank + scatter ----
    for (int p = lt; p < V; p += HT) {
        const unsigned long long kp = ukey[h][p];
        const int r = (int)(uint32_t)kp;

        const float* roi = rois + (size_t)(b * R + r) * 5;
        const float x1 = roi[1], y1 = roi[2], x2 = roi[3], y2 = roi[4];
        const float4 d4 = *(const float4*)(bbox_pred + ((size_t)(b * R + r) * CNUM + c) * 4);

        int rank = 0;
        for (int j = 0; j < V; ++j)
            rank += (ukey[h][j] < kp);

        const float w  = x2 - x1 + 1.0f;
        const float hh = y2 - y1 + 1.0f;
        const float cx = x1 + 0.5f * w;
        const float cy = y1 + 0.5f * hh;
        const float pcx = d4.x * 0.1f * w + cx;
        const float pcy = d4.y * 0.1f * hh + cy;
        const float pw  = expf(d4.z * 0.2f) * w;
        const float ph  = expf(d4.w * 0.2f) * hh;

        float nx1 = pcx - 0.5f * pw;
        float ny1 = pcy - 0.5f * ph;
        float nx2 = pcx + 0.5f * pw;
        float ny2 = pcy + 0.5f * ph;
        nx1 = fminf(fmaxf(nx1, 0.0f), w_im - 1.0f);
        nx2 = fminf(fmaxf(nx2, 0.0f), w_im - 1.0f);
        ny1 = fminf(fmaxf(ny1, 0.0f), h_im - 1.0f);
        ny2 = fminf(fmaxf(ny2, 0.0f), h_im - 1.0f);

        sx1[h][rank] = nx1; sy1[h][rank] = ny1;
        sx2[h][rank] = nx2; sy2[h][rank] = ny2;
        sar[h][rank] = fmaxf(nx2 - nx1, 0.0f) * fmaxf(ny2 - ny1, 0.0f);
    }
    CHAIN_SYNC(h);

    if (V <= VMAX) {
        // ---- matrix NMS mask build (W <= 2 words/row) ----
        const int W = (V + 63) >> 6;
        for (int t = lt; t < V * W; t += HT) {
            const int i = t / W;
            const int w = t - i * W;
            const float ax1 = sx1[h][i], ay1 = sy1[h][i];
            const float ax2 = sx2[h][i], ay2 = sy2[h][i];
            const float aa  = sar[h][i];
            unsigned long long bits = 0ULL;
            const int j0 = max(i + 1, w << 6);
            const int j1 = min(V, (w + 1) << 6);
            for (int j = j0; j < j1; ++j) {
                const float xx1 = fmaxf(ax1, sx1[h][j]);
                const float yy1 = fmaxf(ay1, sy1[h][j]);
                const float xx2 = fminf(ax2, sx2[h][j]);
                const float yy2 = fminf(ay2, sy2[h][j]);
                const float inter = fmaxf(xx2 - xx1, 0.0f) * fmaxf(yy2 - yy1, 0.0f);
                const float iou = inter / (aa + sar[h][j] - inter + 1e-9f);
                if (iou > NMS_THR) bits |= 1ULL << (j & 63);
            }
            sup[h][i][w] = bits;
        }
        CHAIN_SYNC(h);

        // ---- chain-leader register-word greedy: kept bitmask only ----
        if (lt == 0) {
            unsigned long long r0 = 0, r1 = 0;
            if (V >= 64) { r0 = ~0ULL; r1 = (V >= 128) ? ~0ULL : ((V > 64) ? ((1ULL << (V - 64)) - 1ULL) : 0ULL); }
            else if (V > 0) r0 = (1ULL << V) - 1ULL;
            unsigned long long k0 = 0, k1 = 0;
            int k = 0;
            for (;;) {
                int i;
                if (r0)      { const int t = __ffsll((long long)r0) - 1; r0 &= ~(1ULL << t); k0 |= 1ULL << t; i = t; }
                else if (r1) { const int t = __ffsll((long long)r1) - 1; r1 &= ~(1ULL << t); k1 |= 1ULL << t; i = 64 + t; }
                else break;
                r0 &= ~sup[h][i][0];
                if (V > 64) r1 &= ~sup[h][i][1];
                ++k;
            }
            keptw[h][0] = k0; keptw[h][1] = k1;
            g_cnt[b][cls] = k;
        }
        CHAIN_SYNC(h);

        // ---- parallel store of kept dets (vectorized: float4 + float) ----
        for (int i = lt; i < V; i += HT) {
            const int w = i >> 6;
            const unsigned long long word = keptw[h][w];
            if ((word >> (i & 63)) & 1ULL) {
                int k = __popcll(word & ((1ULL << (i & 63)) - 1ULL));
                if (w) k += __popcll(keptw[h][0]);
                if (k < NP) {
                    float4 v4 = make_float4(sx1[h][i], sy1[h][i], sx2[h][i], sy2[h][i]);
                    *(float4*)(&g_dets[b][cls][k][0]) = v4;
                    g_dets[b][cls][k][4] = (float)c;
                }
            }
        }
    } else {
        // ---- fallback: barrier-loop greedy NMS (rarely taken) ----
        for (int i = lt; i < V; i += HT) keep[h][i] = 1;
        CHAIN_SYNC(h);
        for (int i = 0; i < V; ++i) {
            if (keep[h][i]) {
                const float ax1 = sx1[h][i], ay1 = sy1[h][i];
                const float ax2 = sx2[h][i], ay2 = sy2[h][i];
                const float aa  = sar[h][i];
                for (int j = i + 1 + lt; j < V; j += HT) {
                    if (keep[h][j]) {
                        const float xx1 = fmaxf(ax1, sx1[h][j]);
                        const float yy1 = fmaxf(ay1, sy1[h][j]);
                        const float xx2 = fminf(ax2, sx2[h][j]);
                        const float yy2 = fminf(ay2, sy2[h][j]);
                        const float inter = fmaxf(xx2 - xx1, 0.0f) * fmaxf(yy2 - yy1, 0.0f);
                        const float iou = inter / (aa + sar[h][j] - inter + 1e-9f);
                        if (iou > NMS_THR) keep[h][j] = 0;
                    }
                }
            }
            CHAIN_SYNC(h);
        }
        if (lt == 0) {
            int k = 0;
            for (int i = 0; i < V; ++i) {
                if (keep[h][i]) {
                    if (k < NP) {
                        float4 v4 = make_float4(sx1[h][i], sy1[h][i], sx2[h][i], sy2[h][i]);
                        *(float4*)(&g_dets[b][cls][k][0]) = v4;
                        g_dets[b][cls][k][4] = (float)c;
                    }
                    ++k;
                }
            }
            g_cnt[b][cls] = k;
        }
    }

    // ======== last-block-done combine (whole CTA) ========
    __threadfence();
    __syncthreads();

    if (tid == 0) is_last = (atomicAdd(&g_done, 1u) == NBLK - 1u) ? 1u : 0u;
    __syncthreads();
    if (!is_last) return;

    for (int t = tid; t < BATCH * NCLS; t += NT)
        cnts[t / NCLS][t % NCLS] = g_cnt[t / NCLS][t % NCLS];
    __syncthreads();

    // per-image inclusive prefix via chunked warp scans
    if (tid < 64) {
        const int w = tid >> 5;     // image
        const int l = tid & 31;
        int carry = 0;
        #pragma unroll
        for (int ch = 0; ch < 3; ++ch) {
            const int cc = ch * 32 + l;
            int v = (cc < NCLS) ? cnts[w][cc] : 0;
            #pragma unroll
            for (int off = 1; off < 32; off <<= 1) {
                const int n_ = __shfl_up_sync(0xffffffffu, v, off);
                if (l >= off) v += n_;
            }
            if (cc < NCLS) incl[w][cc] = v + carry;
            carry += __shfl_sync(0xffffffffu, v, 31);
        }
    }
    __syncthreads();

    // single fused pass: each slot k<NP gets either its det or zeros
    for (int t = tid; t < BATCH * NP; t += NT) {
        const int bb = t / NP;
        const int k  = t - bb * NP;
        const int total = incl[bb][NCLS - 1];
        const int n = total < NP ? total : NP;
        float* gout = out + (size_t)bb * NP * 5 + (size_t)k * 5;
        if (k < n) {
            int lo = 0, hi = NCLS - 1;
            while (lo < hi) {
                const int mid = (lo + hi) >> 1;
                if (incl[bb][mid] > k) hi = mid; else lo = mid + 1;
            }
            const int cc = lo;
            const int tt = k - (incl[bb][cc] - cnts[bb][cc]);
            const float4 v4 = *(const float4*)(&g_dets[bb][cc][tt][0]);
            gout[0] = v4.x; gout[1] = v4.y; gout[2] = v4.z; gout[3] = v4.w;
            gout[4] = g_dets[bb][cc][tt][4];
        } else {
            gout[0] = 0.0f; gout[1] = 0.0f; gout[2] = 0.0f; gout[3] = 0.0f;
            gout[4] = 0.0f;
        }
        if (k == 0 && out_size >= BATCH * NP * 5 + BATCH)
            out[BATCH * NP * 5 + bb] = (float)n;
    }

    const int base = BATCH * NP * 5 + BATCH;
    for (int i = base + tid; i < out_size; i += NT) out[i] = 0.0f;

    __syncthreads();
    if (tid == 0) g_done = 0;   // reset for next graph replay
}

extern "C" void kernel_launch(void* const* d_in, const int* in_sizes, int n_in,
                              void* d_out, int out_size)
{
    const float* cls_prob  = (const float*)d_in[0];
    const float* rois      = (const float*)d_in[1];
    const float* bbox_pred = (const float*)d_in[2];
    const float* im_info   = (const float*)d_in[3];
    const float* thr       = (const float*)d_in[4];
    float* out = (float*)d_out;

    const int R = in_sizes[0] / (BATCH * CNUM);      // 1000

    dim3 grid(NCLS / 2, BATCH);                      // 40 x 2 = 80 CTAs
    fused_kernel<<<grid, NT>>>(cls_prob, rois, bbox_pred, im_info, thr,
                               out, out_size, R);
}

// round 17
// speedup vs baseline: 1.0094x; 1.0094x over previous
#include <cuda_runtime.h>
#include <math_constants.h>
#include <stdint.h>

#define BATCH   2
#define CNUM    81
#define NCLS    (CNUM - 1)
#define NP      CNUM
#define VCAP    512          // storage cap per chain (V never near this)
#define VMAX    128          // fast-path cap for matrix NMS
#define NMS_THR 0.3f
#define NT      512          // threads per CTA (2 chains x 256)
#define HT      256          // threads per chain
#define RPT     4            // hoisted scores per thread (HT*4 = 1024 >= R)
#define NBLK    (NCLS / 2 * BATCH)   // 80 CTAs

// det rows padded to 8 floats for vectorized access
__device__ __align__(16) float g_dets[BATCH][NCLS][NP][8];
__device__ int   g_cnt[BATCH][NCLS];
__device__ unsigned int g_done = 0;

// named barrier for one 256-thread chain (id 1 or 2)
#define CHAIN_SYNC(h) asm volatile("bar.sync %0, %1;" :: "r"((h) + 1), "r"(HT) : "memory")

__global__ void __launch_bounds__(NT)
fused_kernel(const float* __restrict__ cls_prob,   // (B,R,C)
             const float* __restrict__ rois,       // (B,R,5)
             const float* __restrict__ bbox_pred,  // (B,R,4C)
             const float* __restrict__ im_info,    // (B,3)
             const float* __restrict__ thr,        // (C,)
             float* __restrict__ out, int out_size,
             int R)
{
    const int tid  = threadIdx.x;
    const int h    = tid >> 8;          // chain (0/1)
    const int lt   = tid & (HT - 1);    // lane within chain
    const int lane = tid & 31;
    const int b    = blockIdx.y;
    const int cls  = blockIdx.x * 2 + h;   // 0..79
    const int c    = cls + 1;              // class id 1..80

    __shared__ unsigned long long ukey[2][VCAP];
    __shared__ float sx1[2][VCAP], sy1[2][VCAP], sx2[2][VCAP], sy2[2][VCAP], sar[2][VCAP];
    __shared__ unsigned long long sup[2][VMAX][2];
    __shared__ unsigned long long keptw[2][2];
    __shared__ unsigned char keep[2][VCAP];       // fallback only
    __shared__ int svcnt[2];
    __shared__ unsigned int is_last;
    __shared__ int scnt[BATCH][NCLS];    // per-class count (epilogue)
    __shared__ int sinc[BATCH][NCLS];    // inclusive prefix (epilogue)

    if (lt == 0) svcnt[h] = 0;
    CHAIN_SYNC(h);

    const float h_im = im_info[b * 3 + 0];
    const float w_im = im_info[b * 3 + 1];
    const float th   = thr[c];

    // ---- pass 1: hoisted score loads + warp-aggregated compaction ----
    float sc[RPT];
    #pragma unroll
    for (int it = 0; it < RPT; ++it) {
        const int rr = lt + it * HT;
        sc[it] = (rr < R) ? cls_prob[(size_t)(b * R + rr) * CNUM + c] : -1.0f;
    }
    #pragma unroll
    for (int it = 0; it < RPT; ++it) {
        const int rr = lt + it * HT;
        const bool valid = sc[it] > th;
        const unsigned mask = __ballot_sync(0xffffffffu, valid);
        if (mask) {
            const int leader = __ffs(mask) - 1;
            int base = 0;
            if (lane == leader) base = atomicAdd(&svcnt[h], __popc(mask));
            base = __shfl_sync(0xffffffffu, base, leader);
            if (valid) {
                const int pos = base + __popc(mask & ((1u << lane) - 1u));
                if (pos < VCAP) {
                    const uint32_t ub = __float_as_uint(sc[it]) ^ 0x80000000u;
                    ukey[h][pos] = ((unsigned long long)(~ub) << 32) | (uint32_t)rr;
                }
            }
        }
    }
    CHAIN_SYNC(h);

    const int V = min(svcnt[h], VCAP);

    // ---- fused decode + rank + scatter ----
    for (int p = lt; p < V; p += HT) {
        const unsigned long long kp = ukey[h][p];
        const int r = (int)(uint32_t)kp;

        const float* roi = rois + (size_t)(b * R + r) * 5;
        const float x1 = roi[1], y1 = roi[2], x2 = roi[3], y2 = roi[4];
        const float4 d4 = *(const float4*)(bbox_pred + ((size_t)(b * R + r) * CNUM + c) * 4);

        int rank = 0;
        for (int j = 0; j < V; ++j)
            rank += (ukey[h][j] < kp);

        const float w  = x2 - x1 + 1.0f;
        const float hh = y2 - y1 + 1.0f;
        const float cx = x1 + 0.5f * w;
        const float cy = y1 + 0.5f * hh;
        const float pcx = d4.x * 0.1f * w + cx;
        const float pcy = d4.y * 0.1f * hh + cy;
        const float pw  = expf(d4.z * 0.2f) * w;
        const float ph  = expf(d4.w * 0.2f) * hh;

        float nx1 = pcx - 0.5f * pw;
        float ny1 = pcy - 0.5f * ph;
        float nx2 = pcx + 0.5f * pw;
        float ny2 = pcy + 0.5f * ph;
        nx1 = fminf(fmaxf(nx1, 0.0f), w_im - 1.0f);
        nx2 = fminf(fmaxf(nx2, 0.0f), w_im - 1.0f);
        ny1 = fminf(fmaxf(ny1, 0.0f), h_im - 1.0f);
        ny2 = fminf(fmaxf(ny2, 0.0f), h_im - 1.0f);

        sx1[h][rank] = nx1; sy1[h][rank] = ny1;
        sx2[h][rank] = nx2; sy2[h][rank] = ny2;
        sar[h][rank] = fmaxf(nx2 - nx1, 0.0f) * fmaxf(ny2 - ny1, 0.0f);
    }
    CHAIN_SYNC(h);

    if (V <= VMAX) {
        // ---- matrix NMS mask build (W <= 2 words/row) ----
        const int W = (V + 63) >> 6;
        for (int t = lt; t < V * W; t += HT) {
            const int i = t / W;
            const int w = t - i * W;
            const float ax1 = sx1[h][i], ay1 = sy1[h][i];
            const float ax2 = sx2[h][i], ay2 = sy2[h][i];
            const float aa  = sar[h][i];
            unsigned long long bits = 0ULL;
            const int j0 = max(i + 1, w << 6);
            const int j1 = min(V, (w + 1) << 6);
            for (int j = j0; j < j1; ++j) {
                const float xx1 = fmaxf(ax1, sx1[h][j]);
                const float yy1 = fmaxf(ay1, sy1[h][j]);
                const float xx2 = fminf(ax2, sx2[h][j]);
                const float yy2 = fminf(ay2, sy2[h][j]);
                const float inter = fmaxf(xx2 - xx1, 0.0f) * fmaxf(yy2 - yy1, 0.0f);
                const float iou = inter / (aa + sar[h][j] - inter + 1e-9f);
                if (iou > NMS_THR) bits |= 1ULL << (j & 63);
            }
            sup[h][i][w] = bits;
        }
        CHAIN_SYNC(h);

        // ---- chain-leader register-word greedy: kept bitmask only ----
        if (lt == 0) {
            unsigned long long r0 = 0, r1 = 0;
            if (V >= 64) { r0 = ~0ULL; r1 = (V >= 128) ? ~0ULL : ((V > 64) ? ((1ULL << (V - 64)) - 1ULL) : 0ULL); }
            else if (V > 0) r0 = (1ULL << V) - 1ULL;
            unsigned long long k0 = 0, k1 = 0;
            int k = 0;
            for (;;) {
                int i;
                if (r0)      { const int t = __ffsll((long long)r0) - 1; r0 &= ~(1ULL << t); k0 |= 1ULL << t; i = t; }
                else if (r1) { const int t = __ffsll((long long)r1) - 1; r1 &= ~(1ULL << t); k1 |= 1ULL << t; i = 64 + t; }
                else break;
                r0 &= ~sup[h][i][0];
                if (V > 64) r1 &= ~sup[h][i][1];
                ++k;
            }
            keptw[h][0] = k0; keptw[h][1] = k1;
            g_cnt[b][cls] = k;
        }
        CHAIN_SYNC(h);

        // ---- parallel store of kept dets (vectorized: float4 + float) ----
        for (int i = lt; i < V; i += HT) {
            const int w = i >> 6;
            const unsigned long long word = keptw[h][w];
            if ((word >> (i & 63)) & 1ULL) {
                int k = __popcll(word & ((1ULL << (i & 63)) - 1ULL));
                if (w) k += __popcll(keptw[h][0]);
                if (k < NP) {
                    float4 v4 = make_float4(sx1[h][i], sy1[h][i], sx2[h][i], sy2[h][i]);
                    *(float4*)(&g_dets[b][cls][k][0]) = v4;
                    g_dets[b][cls][k][4] = (float)c;
                }
            }
        }
    } else {
        // ---- fallback: barrier-loop greedy NMS (rarely taken) ----
        for (int i = lt; i < V; i += HT) keep[h][i] = 1;
        CHAIN_SYNC(h);
        for (int i = 0; i < V; ++i) {
            if (keep[h][i]) {
                const float ax1 = sx1[h][i], ay1 = sy1[h][i];
                const float ax2 = sx2[h][i], ay2 = sy2[h][i];
                const float aa  = sar[h][i];
                for (int j = i + 1 + lt; j < V; j += HT) {
                    if (keep[h][j]) {
                        const float xx1 = fmaxf(ax1, sx1[h][j]);
                        const float yy1 = fmaxf(ay1, sy1[h][j]);
                        const float xx2 = fminf(ax2, sx2[h][j]);
                        const float yy2 = fminf(ay2, sy2[h][j]);
                        const float inter = fmaxf(xx2 - xx1, 0.0f) * fmaxf(yy2 - yy1, 0.0f);
                        const float iou = inter / (aa + sar[h][j] - inter + 1e-9f);
                        if (iou > NMS_THR) keep[h][j] = 0;
                    }
                }
            }
            CHAIN_SYNC(h);
        }
        if (lt == 0) {
            int k = 0;
            for (int i = 0; i < V; ++i) {
                if (keep[h][i]) {
                    if (k < NP) {
                        float4 v4 = make_float4(sx1[h][i], sy1[h][i], sx2[h][i], sy2[h][i]);
                        *(float4*)(&g_dets[b][cls][k][0]) = v4;
                        g_dets[b][cls][k][4] = (float)c;
                    }
                    ++k;
                }
            }
            g_cnt[b][cls] = k;
        }
    }

    // ======== last-block-done combine (whole CTA) ========
    __threadfence();
    __syncthreads();

    if (tid == 0) is_last = (atomicAdd(&g_done, 1u) == NBLK - 1u) ? 1u : 0u;
    __syncthreads();
    if (!is_last) return;

    // scan warps load g_cnt directly (hoisted, MLP=3) — no NT-wide staging
    if (tid < 64) {
        const int w = tid >> 5;     // image
        const int l = tid & 31;
        int vload[3];
        #pragma unroll
        for (int ch = 0; ch < 3; ++ch) {
            const int cc = ch * 32 + l;
            vload[ch] = (cc < NCLS) ? g_cnt[w][cc] : 0;
        }
        int carry = 0;
        #pragma unroll
        for (int ch = 0; ch < 3; ++ch) {
            const int cc = ch * 32 + l;
            int v = vload[ch];
            const int orig = v;
            #pragma unroll
            for (int off = 1; off < 32; off <<= 1) {
                const int n_ = __shfl_up_sync(0xffffffffu, v, off);
                if (l >= off) v += n_;
            }
            if (cc < NCLS) {
                sinc[w][cc] = v + carry;
                scnt[w][cc] = orig;
            }
            carry += __shfl_sync(0xffffffffu, v, 31);
        }
    }
    __syncthreads();

    // single fused pass: each slot k<NP gets either its det or zeros
    for (int t = tid; t < BATCH * NP; t += NT) {
        const int bb = t / NP;
        const int k  = t - bb * NP;
        const int total = sinc[bb][NCLS - 1];
        const int n = total < NP ? total : NP;
        float* gout = out + (size_t)bb * NP * 5 + (size_t)k * 5;
        if (k < n) {
            int lo = 0, hi = NCLS - 1;
            while (lo < hi) {
                const int mid = (lo + hi) >> 1;
                if (sinc[bb][mid] > k) hi = mid; else lo = mid + 1;
            }
            const int cc = lo;
            const int tt = k - (sinc[bb][cc] - scnt[bb][cc]);
            const float4 v4 = *(const float4*)(&g_dets[bb][cc][tt][0]);
            gout[0] = v4.x; gout[1] = v4.y; gout[2] = v4.z; gout[3] = v4.w;
            gout[4] = g_dets[bb][cc][tt][4];
        } else {
            gout[0] = 0.0f; gout[1] = 0.0f; gout[2] = 0.0f; gout[3] = 0.0f;
            gout[4] = 0.0f;
        }
        if (k == 0 && out_size >= BATCH * NP * 5 + BATCH)
            out[BATCH * NP * 5 + bb] = (float)n;
    }

    const int base = BATCH * NP * 5 + BATCH;
    for (int i = base + tid; i < out_size; i += NT) out[i] = 0.0f;

    __syncthreads();
    if (tid == 0) g_done = 0;   // reset for next graph replay
}

extern "C" void kernel_launch(void* const* d_in, const int* in_sizes, int n_in,
                              void* d_out, int out_size)
{
    const float* cls_prob  = (const float*)d_in[0];
    const float* rois      = (const float*)d_in[1];
    const float* bbox_pred = (const float*)d_in[2];
    const float* im_info   = (const float*)d_in[3];
    const float* thr       = (const float*)d_in[4];
    float* out = (float*)d_out;

    const int R = in_sizes[0] / (BATCH * CNUM);      // 1000

    dim3 grid(NCLS / 2, BATCH);                      // 40 x 2 = 80 CTAs
    fused_kernel<<<grid, NT>>>(cls_prob, rois, bbox_pred, im_info, thr,
                               out, out_size, R);
}